// round 10
// baseline (speedup 1.0000x reference)
#include <cuda_runtime.h>
#include <cstdint>

#define NNODES 50000
#define NEDGES 800000
#define DF 128
#define KTOT 256

// ---------------- device scratch ----------------
__device__ int   g_deg[NNODES];
__device__ int   g_fill[NNODES];
__device__ int   g_ptr[NNODES + 1];
__device__ int   g_csr[NEDGES];
__device__ float g_agg[(size_t)NNODES * DF];
__device__ float g_h[(size_t)NNODES * DF];
__device__ uint32_t g_Bhi0[KTOT * 128];   // tf32 bits, [k][n]
__device__ uint32_t g_Blo0[KTOT * 128];
__device__ uint32_t g_Bhi1[KTOT * 128];
__device__ uint32_t g_Blo1[KTOT * 128];
__device__ uint32_t g_Bhi2[KTOT * 64];
__device__ uint32_t g_Blo2[KTOT * 64];
__device__ float g_c0[128];
__device__ float g_c1[128];
__device__ float g_c2[64];

// ---------------- tf32 helpers ----------------
__device__ __forceinline__ uint32_t f2tf(float x) {
    uint32_t u;
    asm("cvt.rna.tf32.f32 %0, %1;" : "=r"(u) : "f"(x));
    return u;
}
__device__ __forceinline__ void mma_tf32(float* d, const uint32_t* a,
                                         uint32_t b0, uint32_t b1) {
    asm volatile(
        "mma.sync.aligned.m16n8k8.row.col.f32.tf32.tf32.f32 "
        "{%0,%1,%2,%3},{%4,%5,%6,%7},{%8,%9},{%0,%1,%2,%3};"
        : "+f"(d[0]), "+f"(d[1]), "+f"(d[2]), "+f"(d[3])
        : "r"(a[0]), "r"(a[1]), "r"(a[2]), "r"(a[3]), "r"(b0), "r"(b1));
}

// ---------------- CSR build ----------------
__global__ void hist_kernel(const int* __restrict__ dst) {
    int e = blockIdx.x * blockDim.x + threadIdx.x;
    if (e < NEDGES) atomicAdd(&g_deg[dst[e]], 1);
}
__global__ void scan_kernel() {
    __shared__ int s[1024];
    int t = threadIdx.x;
    const int CH = (NNODES + 1023) / 1024;
    int start = t * CH, end = min(start + CH, NNODES);
    int local = 0;
    for (int i = start; i < end; i++) local += g_deg[i];
    s[t] = local;
    __syncthreads();
    for (int off = 1; off < 1024; off <<= 1) {
        int v = (t >= off) ? s[t - off] : 0;
        __syncthreads();
        s[t] += v;
        __syncthreads();
    }
    int run = (t == 0) ? 0 : s[t - 1];
    for (int i = start; i < end; i++) {
        g_ptr[i] = run; g_fill[i] = run;
        run += g_deg[i];
        g_deg[i] = 0;                      // self-rezero for graph replay
    }
    if (end == NNODES) g_ptr[NNODES] = run;
}
__global__ void fill_kernel(const int* __restrict__ src, const int* __restrict__ dst) {
    int e = blockIdx.x * blockDim.x + threadIdx.x;
    if (e < NEDGES) {
        int pos = atomicAdd(&g_fill[dst[e]], 1);
        g_csr[pos] = src[e];
    }
}

// ---------------- combine + tf32 split: B[k][n] = (k<DF ? Wl : Wr+Ws), c = bl+bs ----------------
__global__ void combine_kernel(const float* __restrict__ Wl, const float* __restrict__ Wr,
                               const float* __restrict__ Ws, const float* __restrict__ bl,
                               const float* __restrict__ bs, uint32_t* __restrict__ Bhi,
                               uint32_t* __restrict__ Blo, float* __restrict__ bc, int dout) {
    int i = blockIdx.x * blockDim.x + threadIdx.x;
    if (i < KTOT * dout) {
        int k = i / dout, n = i % dout;
        float w = (k < DF) ? Wl[k * dout + n]
                           : Wr[(k - DF) * dout + n] + Ws[(k - DF) * dout + n];
        uint32_t hi = f2tf(w);
        Bhi[i] = hi;
        Blo[i] = f2tf(w - __uint_as_float(hi));
    }
    if (i < dout) bc[i] = bl[i] + bs[i];
}

// ---------------- mean aggregation: warp per node, unroll 8 ----------------
__global__ void agg_kernel(const float* __restrict__ X) {
    int warp = (blockIdx.x * blockDim.x + threadIdx.x) >> 5;
    int lane = threadIdx.x & 31;
    if (warp >= NNODES) return;
    int e0 = g_ptr[warp], e1 = g_ptr[warp + 1];
    const float4* __restrict__ X4 = (const float4*)X;
    float4 a0 = make_float4(0.f, 0.f, 0.f, 0.f);
    float4 a1 = a0, a2 = a0, a3 = a0;
    int e = e0;
    for (; e + 7 < e1; e += 8) {
        int s0 = g_csr[e],     s1 = g_csr[e + 1], s2 = g_csr[e + 2], s3 = g_csr[e + 3];
        int s4 = g_csr[e + 4], s5 = g_csr[e + 5], s6 = g_csr[e + 6], s7 = g_csr[e + 7];
        float4 v0 = X4[(size_t)s0 * 32 + lane];
        float4 v1 = X4[(size_t)s1 * 32 + lane];
        float4 v2 = X4[(size_t)s2 * 32 + lane];
        float4 v3 = X4[(size_t)s3 * 32 + lane];
        float4 v4 = X4[(size_t)s4 * 32 + lane];
        float4 v5 = X4[(size_t)s5 * 32 + lane];
        float4 v6 = X4[(size_t)s6 * 32 + lane];
        float4 v7 = X4[(size_t)s7 * 32 + lane];
        a0.x += v0.x; a0.y += v0.y; a0.z += v0.z; a0.w += v0.w;
        a1.x += v1.x; a1.y += v1.y; a1.z += v1.z; a1.w += v1.w;
        a2.x += v2.x; a2.y += v2.y; a2.z += v2.z; a2.w += v2.w;
        a3.x += v3.x; a3.y += v3.y; a3.z += v3.z; a3.w += v3.w;
        a0.x += v4.x; a0.y += v4.y; a0.z += v4.z; a0.w += v4.w;
        a1.x += v5.x; a1.y += v5.y; a1.z += v5.z; a1.w += v5.w;
        a2.x += v6.x; a2.y += v6.y; a2.z += v6.z; a2.w += v6.w;
        a3.x += v7.x; a3.y += v7.y; a3.z += v7.z; a3.w += v7.w;
    }
    for (; e < e1; e++) {
        int s0 = g_csr[e];
        float4 v0 = X4[(size_t)s0 * 32 + lane];
        a0.x += v0.x; a0.y += v0.y; a0.z += v0.z; a0.w += v0.w;
    }
    float sc = 1.0f / (float)max(e1 - e0, 1);
    float4 r;
    r.x = (a0.x + a1.x + a2.x + a3.x) * sc;
    r.y = (a0.y + a1.y + a2.y + a3.y) * sc;
    r.z = (a0.z + a1.z + a2.z + a3.z) * sc;
    r.w = (a0.w + a1.w + a2.w + a3.w) * sc;
    ((float4*)g_agg)[(size_t)warp * 32 + lane] = r;
}

// ---------------- tf32-split MMA GEMM: C = [Aagg | Ax] @ B + bias (+relu) ----------------
// BM=64, 256 threads = 8 warps (2m x 4n), warp tile 32 x (BN/4). K chunks of 32.
template <int BN, bool RELU>
__global__ void __launch_bounds__(256, 2)
tfgemm_kernel(const float* __restrict__ Aagg, const float* __restrict__ Ax,
              const uint32_t* __restrict__ Bhi, const uint32_t* __restrict__ Blo,
              const float* __restrict__ bias, float* __restrict__ C, int M) {
    constexpr int BM = 64, BK = 32;
    constexpr int NW = BN / 4;         // warp n-width: 32 or 16
    constexpr int NT = NW / 8;         // n-tiles per warp: 4 or 2
    constexpr int ASTR = BK + 4;       // 36
    constexpr int BSTR = BN + 4;
    constexpr int BQ = BN / 32;        // uint4 B loads per thread per buffer

    extern __shared__ uint32_t sm[];
    uint32_t* Ashi = sm;                       // [64][ASTR]
    uint32_t* Aslo = Ashi + BM * ASTR;
    uint32_t* Bshi = Aslo + BM * ASTR;         // [32][BSTR]
    uint32_t* Bslo = Bshi + BK * BSTR;

    int tid = threadIdx.x, wid = tid >> 5, lane = tid & 31;
    int warpM = wid >> 2;              // 0..1
    int warpN = wid & 3;               // 0..3
    int m0 = blockIdx.x * BM;
    int g = lane >> 2, tg = lane & 3;  // frag row-group / col-in-group

    float acc[2][NT][4];
#pragma unroll
    for (int i = 0; i < 2; i++)
#pragma unroll
        for (int j = 0; j < NT; j++)
#pragma unroll
            for (int q = 0; q < 4; q++) acc[i][j][q] = 0.f;

#pragma unroll
    for (int ch = 0; ch < KTOT / BK; ch++) {
        int kc = ch * BK;
        const float* Abase = (kc < DF) ? Aagg : Ax;
        int kco = kc & (DF - 1);
        // stage A (fp32 -> tf32 hi/lo once per chunk): 64x32 el, 2 float4/thread
#pragma unroll
        for (int i = 0; i < 2; i++) {
            int f4 = tid + i * 256;
            int row = f4 >> 3, c4 = (f4 & 7) * 4;
            int m = m0 + row;
            float4 v = (m < M) ? *(const float4*)(Abase + (size_t)m * DF + kco + c4)
                               : make_float4(0.f, 0.f, 0.f, 0.f);
            uint32_t h0 = f2tf(v.x), h1 = f2tf(v.y), h2 = f2tf(v.z), h3 = f2tf(v.w);
            uint32_t* ph = &Ashi[row * ASTR + c4];
            uint32_t* pl = &Aslo[row * ASTR + c4];
            ph[0] = h0; ph[1] = h1; ph[2] = h2; ph[3] = h3;
            pl[0] = f2tf(v.x - __uint_as_float(h0));
            pl[1] = f2tf(v.y - __uint_as_float(h1));
            pl[2] = f2tf(v.z - __uint_as_float(h2));
            pl[3] = f2tf(v.w - __uint_as_float(h3));
        }
        // stage B hi/lo: 32 x BN u32 each
#pragma unroll
        for (int i = 0; i < BQ; i++) {
            int q = tid + i * 256;
            int row = q / (BN / 4), c4 = (q % (BN / 4)) * 4;
            *(uint4*)&Bshi[row * BSTR + c4] = *(const uint4*)&Bhi[(size_t)(kc + row) * BN + c4];
            *(uint4*)&Bslo[row * BSTR + c4] = *(const uint4*)&Blo[(size_t)(kc + row) * BN + c4];
        }
        __syncthreads();
#pragma unroll
        for (int ks = 0; ks < 4; ks++) {
            int k8 = ks * 8;
            uint32_t ahi[2][4], alo[2][4];
#pragma unroll
            for (int mt = 0; mt < 2; mt++) {
                int r = warpM * 32 + mt * 16 + g;
                int c = k8 + tg;
                ahi[mt][0] = Ashi[r * ASTR + c];
                ahi[mt][1] = Ashi[(r + 8) * ASTR + c];
                ahi[mt][2] = Ashi[r * ASTR + c + 4];
                ahi[mt][3] = Ashi[(r + 8) * ASTR + c + 4];
                alo[mt][0] = Aslo[r * ASTR + c];
                alo[mt][1] = Aslo[(r + 8) * ASTR + c];
                alo[mt][2] = Aslo[r * ASTR + c + 4];
                alo[mt][3] = Aslo[(r + 8) * ASTR + c + 4];
            }
#pragma unroll
            for (int nt = 0; nt < NT; nt++) {
                int n = warpN * NW + nt * 8 + g;
                int k = k8 + tg;
                uint32_t bh0 = Bshi[k * BSTR + n];
                uint32_t bh1 = Bshi[(k + 4) * BSTR + n];
                uint32_t bl0_ = Bslo[k * BSTR + n];
                uint32_t bl1_ = Bslo[(k + 4) * BSTR + n];
#pragma unroll
                for (int mt = 0; mt < 2; mt++) {
                    mma_tf32(acc[mt][nt], ahi[mt], bh0, bh1);   // hi*hi
                    mma_tf32(acc[mt][nt], ahi[mt], bl0_, bl1_); // hi*lo
                    mma_tf32(acc[mt][nt], alo[mt], bh0, bh1);   // lo*hi
                }
            }
        }
        __syncthreads();
    }

    // epilogue: fragment layout c0:(g, tg*2) c1:(g, tg*2+1) c2:(g+8, ..) c3
#pragma unroll
    for (int mt = 0; mt < 2; mt++) {
#pragma unroll
        for (int nt = 0; nt < NT; nt++) {
            int cb = warpN * NW + nt * 8 + tg * 2;
            float bx = bias[cb], by = bias[cb + 1];
            int r0 = m0 + warpM * 32 + mt * 16 + g;
            if (r0 < M) {
                float2 o;
                o.x = acc[mt][nt][0] + bx;
                o.y = acc[mt][nt][1] + by;
                if (RELU) { o.x = fmaxf(o.x, 0.f); o.y = fmaxf(o.y, 0.f); }
                *(float2*)&C[(size_t)r0 * BN + cb] = o;
            }
            int r1 = r0 + 8;
            if (r1 < M) {
                float2 o;
                o.x = acc[mt][nt][2] + bx;
                o.y = acc[mt][nt][3] + by;
                if (RELU) { o.x = fmaxf(o.x, 0.f); o.y = fmaxf(o.y, 0.f); }
                *(float2*)&C[(size_t)r1 * BN + cb] = o;
            }
        }
    }
}

// ---------------- launch ----------------
extern "C" void kernel_launch(void* const* d_in, const int* in_sizes, int n_in,
                              void* d_out, int out_size) {
    const float* x = (const float*)d_in[0];
    const int* ei = (const int*)d_in[1];       // int32 (JAX canonicalized)
    const float* Wl0 = (const float*)d_in[4];
    const float* bl0 = (const float*)d_in[5];
    const float* Wr0 = (const float*)d_in[6];
    const float* Ws0 = (const float*)d_in[7];
    const float* bs0 = (const float*)d_in[8];
    const float* Wl1 = (const float*)d_in[9];
    const float* bl1 = (const float*)d_in[10];
    const float* Wr1 = (const float*)d_in[11];
    const float* Ws1 = (const float*)d_in[12];
    const float* bs1 = (const float*)d_in[13];
    const float* Wl2 = (const float*)d_in[14];
    const float* bl2 = (const float*)d_in[15];
    const float* Wr2 = (const float*)d_in[16];
    const float* Ws2 = (const float*)d_in[17];
    const float* bs2 = (const float*)d_in[18];

    const int* src = ei;
    const int* dst = ei + NEDGES;

    float *agg, *h, *c0, *c1, *c2;
    uint32_t *Bhi0, *Blo0, *Bhi1, *Blo1, *Bhi2, *Blo2;
    cudaGetSymbolAddress((void**)&agg, g_agg);
    cudaGetSymbolAddress((void**)&h, g_h);
    cudaGetSymbolAddress((void**)&Bhi0, g_Bhi0);
    cudaGetSymbolAddress((void**)&Blo0, g_Blo0);
    cudaGetSymbolAddress((void**)&Bhi1, g_Bhi1);
    cudaGetSymbolAddress((void**)&Blo1, g_Blo1);
    cudaGetSymbolAddress((void**)&Bhi2, g_Bhi2);
    cudaGetSymbolAddress((void**)&Blo2, g_Blo2);
    cudaGetSymbolAddress((void**)&c0, g_c0);
    cudaGetSymbolAddress((void**)&c1, g_c1);
    cudaGetSymbolAddress((void**)&c2, g_c2);

    // dynamic smem: BN=128 -> 2*64*36 + 2*32*132 u32 = 52224 B; BN=64 -> 35840 B
    constexpr int SM128 = (2 * 64 * 36 + 2 * 32 * 132) * 4;
    constexpr int SM64 = (2 * 64 * 36 + 2 * 32 * 68) * 4;
    cudaFuncSetAttribute(tfgemm_kernel<128, true>,
                         cudaFuncAttributeMaxDynamicSharedMemorySize, SM128);
    cudaFuncSetAttribute(tfgemm_kernel<64, false>,
                         cudaFuncAttributeMaxDynamicSharedMemorySize, SM64);

    // CSR build
    hist_kernel<<<(NEDGES + 255) / 256, 256>>>(dst);
    scan_kernel<<<1, 1024>>>();
    fill_kernel<<<(NEDGES + 255) / 256, 256>>>(src, dst);

    int aggGrid = (NNODES * 32 + 255) / 256;
    int gemmGrid = (NNODES + 63) / 64;         // 782

    // layer 0 aggregation (profiled slot)
    agg_kernel<<<aggGrid, 256>>>(x);

    // weight fusion + tf32 split
    combine_kernel<<<(KTOT * 128 + 255) / 256, 256>>>(Wl0, Wr0, Ws0, bl0, bs0, Bhi0, Blo0, c0, 128);
    combine_kernel<<<(KTOT * 128 + 255) / 256, 256>>>(Wl1, Wr1, Ws1, bl1, bs1, Bhi1, Blo1, c1, 128);
    combine_kernel<<<(KTOT * 64 + 255) / 256, 256>>>(Wl2, Wr2, Ws2, bl2, bs2, Bhi2, Blo2, c2, 64);

    // layer 0: h = relu([agg(x) | x] @ B0 + c0)
    tfgemm_kernel<128, true><<<gemmGrid, 256, SM128>>>(agg, x, Bhi0, Blo0, c0, h, NNODES);
    // layer 1
    agg_kernel<<<aggGrid, 256>>>(h);
    tfgemm_kernel<128, true><<<gemmGrid, 256, SM128>>>(agg, h, Bhi1, Blo1, c1, h, NNODES);
    // layer 2
    agg_kernel<<<aggGrid, 256>>>(h);
    tfgemm_kernel<64, false><<<gemmGrid, 256, SM64>>>(agg, h, Bhi2, Blo2, c2, (float*)d_out, NNODES);
}